// round 12
// baseline (speedup 1.0000x reference)
#include <cuda_runtime.h>

#define N 512
#define BATCH 256
#define CHUNKS 16                   // chunks per batch row
#define TPB 128
#define GRID (CHUNKS * BATCH)       // 4096 blocks
#define PROJ_TPB 128

// Scratch (no device allocs allowed)
__device__ __align__(16) float g_u[N];
__device__ __align__(16) float g_v[N];
__device__ float g_partial2[BATCH][CHUNKS];
__device__ int g_done_cnt = 0;      // reduce blocks completed

// ---------------------------------------------------------------------------
// Kernel A (parallel): u[k] = sum_i wh[i]*cu(i)*cos((2k+1) i pi/(2N)),
// same for v. One block per k (512 blocks), 128 threads; deterministic tree.
// cospif arg: (2k+1)*i/1024, numerator < 2^24 -> exact in fp32.
// ---------------------------------------------------------------------------
__global__ void __launch_bounds__(PROJ_TPB)
proj_kernel(const float* __restrict__ wh, const float* __restrict__ wv) {
    const int k = blockIdx.x;
    const int t = threadIdx.x;

    const float c0 = sqrtf(1.0f / N);
    const float c1 = sqrtf(2.0f / N);
    const float two_k_p1 = (float)(2 * k + 1);

    float su = 0.f, sv = 0.f;
    #pragma unroll
    for (int r = 0; r < N / PROJ_TPB; ++r) {         // 4 iters
        int i = r * PROJ_TPB + t;
        float cu = (i == 0) ? c0 : c1;
        float tt = two_k_p1 * (float)i * (1.0f / (2.0f * N));
        float c = cospif(tt) * cu;
        su = fmaf(wh[i], c, su);
        sv = fmaf(wv[i], c, sv);
    }

    __shared__ float ru[PROJ_TPB / 32], rv[PROJ_TPB / 32];
    #pragma unroll
    for (int o = 16; o > 0; o >>= 1) {
        su += __shfl_down_sync(0xffffffffu, su, o);
        sv += __shfl_down_sync(0xffffffffu, sv, o);
    }
    if ((t & 31) == 0) { ru[t >> 5] = su; rv[t >> 5] = sv; }
    __syncthreads();
    if (t == 0) {
        g_u[k] = ru[0] + ru[1] + ru[2] + ru[3];
        g_v[k] = rv[0] + rv[1] + rv[2] + rv[3];
    }
}

// ---------------------------------------------------------------------------
// Kernel B: streaming weighted reduction + fused finish (last-block sigmoid).
// grid = 4096; block (b,c) handles 4096 float4 of row b, chunk c (32 iters).
// Index structure for f = i*TPB + t (TPB=128):
//   v index: (f*4)&511 = 4t  -> per-thread CONSTANT float4 (hoisted)
//   u index: (c*4096+f)*4 >> 9 = c*32 + i -> one broadcast scalar per iter
// MLP: 8 independent front-batched LDG.128 per group; launch_bounds(128,10)
// -> regs <= 51, 10 blocks/SM (40 warps), ~160KB in flight/SM.
// ---------------------------------------------------------------------------
__global__ void __launch_bounds__(TPB, 10)
reduce_kernel(const float* __restrict__ x,
              const float* __restrict__ bias,
              float* __restrict__ out) {
    const int bid = blockIdx.x;
    const int t   = threadIdx.x;
    const int b   = bid >> 4;
    const int c   = bid & (CHUNKS - 1);

    const int f4_per_row   = (N * N) / 4;            // 65536
    const int f4_per_chunk = f4_per_row / CHUNKS;    // 4096
    const int iters        = f4_per_chunk / TPB;     // 32

    const float4* __restrict__ xr =
        reinterpret_cast<const float4*>(x) + (size_t)b * f4_per_row + c * f4_per_chunk;

    const float4 v4 = *reinterpret_cast<const float4*>(&g_v[t * 4]);
    const float* __restrict__ up = g_u + c * (N / CHUNKS);   // up[i], i=0..31

    float acc0 = 0.f, acc1 = 0.f;
    #pragma unroll
    for (int g = 0; g < iters; g += 8) {
        float4 xb[8];
        #pragma unroll
        for (int j = 0; j < 8; ++j)                  // 8 loads, front-batched
            xb[j] = __ldg(xr + (g + j) * TPB + t);

        #pragma unroll
        for (int j = 0; j < 8; ++j) {
            float d = fmaf(xb[j].x, v4.x, fmaf(xb[j].y, v4.y,
                      fmaf(xb[j].z, v4.z, xb[j].w * v4.w)));
            if (j & 1) acc1 = fmaf(up[g + j], d, acc1);
            else       acc0 = fmaf(up[g + j], d, acc0);
        }
    }
    float acc = acc0 + acc1;

    // deterministic block reduction (4 warps)
    __shared__ float red[TPB / 32];
    __shared__ bool  is_last;
    #pragma unroll
    for (int o = 16; o > 0; o >>= 1)
        acc += __shfl_down_sync(0xffffffffu, acc, o);
    if ((t & 31) == 0) red[t >> 5] = acc;
    __syncthreads();
    if (t == 0) {
        float s = red[0] + red[1] + red[2] + red[3];
        g_partial2[b][c] = s;
        __threadfence();
        int old = atomicAdd(&g_done_cnt, 1);
        is_last = (old == GRID - 1);
    }
    __syncthreads();

    // last block: sigmoid over all 256 batch entries (2 per thread), fixed order
    if (is_last) {
        __threadfence();                             // see all partials
        #pragma unroll
        for (int r2 = 0; r2 < BATCH / TPB; ++r2) {
            int bb = r2 * TPB + t;
            float r = bias[0];
            #pragma unroll
            for (int cc = 0; cc < CHUNKS; ++cc) r += g_partial2[bb][cc];
            out[bb] = 1.0f / (1.0f + __expf(-r));
        }
        if (t == 0) g_done_cnt = 0;                  // reset for graph replay
    }
}

extern "C" void kernel_launch(void* const* d_in, const int* in_sizes, int n_in,
                              void* d_out, int out_size) {
    const float* x    = (const float*)d_in[0];
    const float* wh   = (const float*)d_in[1];
    const float* wv   = (const float*)d_in[2];
    const float* bias = (const float*)d_in[3];
    float* out = (float*)d_out;

    proj_kernel<<<N, PROJ_TPB>>>(wh, wv);
    reduce_kernel<<<GRID, TPB>>>(x, bias, out);
}